// round 7
// baseline (speedup 1.0000x reference)
#include <cuda_runtime.h>
#include <cooperative_groups.h>
#include <cstdint>

namespace cg = cooperative_groups;

// ---------------- problem constants ----------------
#define BB 2
#define N0 8192
#define N1 4096
#define N2 2048
#define KNBR 16

// ---------------- one big scratch buffer (no allocs allowed) ----------------
__device__ float g_buf[16 * 1024 * 1024]; // 64 MB

#define ALIGN256(x) (((x) + 255) & ~255)
static const size_t OFF_IDX0  = 0;
static const size_t OFF_IDX1  = ALIGN256(OFF_IDX0  + 2*8192*16);
static const size_t OFF_IDX2  = ALIGN256(OFF_IDX1  + 2*4096*16);
static const size_t OFF_FPS1  = ALIGN256(OFF_IDX2  + 2*2048*16);
static const size_t OFF_FPS2  = ALIGN256(OFF_FPS1  + 2*4096);
static const size_t OFF_POS1  = ALIGN256(OFF_FPS2  + 2*2048);
static const size_t OFF_POS2  = ALIGN256(OFF_POS1  + 2*4096*3);
static const size_t OFF_FEAT0 = ALIGN256(OFF_POS2  + 2*2048*3);
static const size_t OFF_FG1   = ALIGN256(OFF_FEAT0 + 2*8192*64);
static const size_t OFF_FEAT1 = ALIGN256(OFF_FG1   + 2*4096*64);
static const size_t OFF_FG2   = ALIGN256(OFF_FEAT1 + 2*4096*128);
static const size_t OFF_FEAT2 = ALIGN256(OFF_FG2   + 2*2048*128);
static const size_t OFF_NNI1  = ALIGN256(OFF_FEAT2 + 2*2048*256);
static const size_t OFF_NNW1  = ALIGN256(OFF_NNI1  + 2*4096*3);
static const size_t OFF_NNI0  = ALIGN256(OFF_NNW1  + 2*4096*3);
static const size_t OFF_NNW0  = ALIGN256(OFF_NNI0  + 2*8192*3);
static const size_t OFF_FU1P  = ALIGN256(OFF_NNW0  + 2*8192*3);
static const size_t OFF_FU1   = ALIGN256(OFF_FU1P  + 2*4096*128);
static const size_t OFF_FU0   = ALIGN256(OFF_FU1   + 2*4096*128);
static const size_t OFF_FOUT  = ALIGN256(OFF_FU0   + 2*8192*64);
static const size_t OFF_ACAT  = ALIGN256(OFF_FOUT  + 2*8192*64);
static const size_t OFF_WCAT  = ALIGN256(OFF_ACAT  + (size_t)16384*384);

// ---------------- packed f32x2 helpers (exact IEEE RN per lane) ----------------
__device__ __forceinline__ unsigned long long f2pack(float lo, float hi) {
    unsigned long long r;
    asm("mov.b64 %0, {%1, %2};" : "=l"(r) : "f"(lo), "f"(hi));
    return r;
}
__device__ __forceinline__ void f2unpack(unsigned long long v, float& lo, float& hi) {
    asm("mov.b64 {%0, %1}, %2;" : "=f"(lo), "=f"(hi) : "l"(v));
}
__device__ __forceinline__ unsigned long long f2add(unsigned long long a, unsigned long long b) {
    unsigned long long r;
    asm("add.rn.f32x2 %0, %1, %2;" : "=l"(r) : "l"(a), "l"(b));
    return r;
}
__device__ __forceinline__ unsigned long long f2mul(unsigned long long a, unsigned long long b) {
    unsigned long long r;
    asm("mul.rn.f32x2 %0, %1, %2;" : "=l"(r) : "l"(a), "l"(b));
    return r;
}

// ---------------- KNN: brute force, top-16 register insertion ----------------
__global__ void knn_kernel(const float* __restrict__ pos, int N, int* __restrict__ outIdx)
{
    const int TILE = 512;
    __shared__ float sx[512], sy[512], sz[512], sn[512];
    int b = blockIdx.y;
    const float* P = pos + (size_t)b * N * 3;
    int i = blockIdx.x * blockDim.x + threadIdx.x;

    float qx = P[i*3+0], qy = P[i*3+1], qz = P[i*3+2];
    float qn = __fadd_rn(__fadd_rn(__fmul_rn(qx,qx), __fmul_rn(qy,qy)), __fmul_rn(qz,qz));

    float bd[KNBR]; int bi[KNBR];
#pragma unroll
    for (int t = 0; t < KNBR; ++t) { bd[t] = 3.0e38f; bi[t] = -1; }

    for (int j0 = 0; j0 < N; j0 += TILE) {
        for (int t = threadIdx.x; t < TILE; t += blockDim.x) {
            float x = P[(j0+t)*3+0], y = P[(j0+t)*3+1], z = P[(j0+t)*3+2];
            sx[t] = x; sy[t] = y; sz[t] = z;
            sn[t] = __fadd_rn(__fadd_rn(__fmul_rn(x,x), __fmul_rn(y,y)), __fmul_rn(z,z));
        }
        __syncthreads();
        for (int t = 0; t < TILE; ++t) {
            float dot = __fadd_rn(__fadd_rn(__fmul_rn(qx,sx[t]), __fmul_rn(qy,sy[t])), __fmul_rn(qz,sz[t]));
            float d = __fsub_rn(__fadd_rn(qn, sn[t]), __fmul_rn(2.0f, dot));
            if (d < bd[KNBR-1]) {
                bd[KNBR-1] = d; bi[KNBR-1] = j0 + t;
#pragma unroll
                for (int s = KNBR-1; s > 0; --s) {
                    if (bd[s] < bd[s-1]) {
                        float tv = bd[s]; bd[s] = bd[s-1]; bd[s-1] = tv;
                        int ti = bi[s]; bi[s] = bi[s-1]; bi[s-1] = ti;
                    }
                }
            }
        }
        __syncthreads();
    }
    int* O = outIdx + ((size_t)b * N + i) * KNBR;
#pragma unroll
    for (int t = 0; t < KNBR; ++t) O[t] = bi[t];
}

// ---------------- FPS v6: 4-CTA cluster per batch, DSMEM broadcast + cluster.sync ----------
// Each CTA owns a contiguous chunk of N/CPB points. Distances >= 0 -> fp32 bits
// monotone as u32. All FP math identical to single-block version (per-lane f32x2).
template<int PQ, int CPB>  // PQ pairs/thread; chunk = 1024*PQ points per CTA
__global__ __launch_bounds__(512, 1) __cluster_dims__(CPB, 1, 1)
void fps6_kernel(const float* __restrict__ pos, int N, int npoint,
                 int* __restrict__ outIdx, float* __restrict__ outPos)
{
    const int NT = 512;
    cg::cluster_group cluster = cg::this_cluster();
    int rank = (int)cluster.block_rank();
    int b = blockIdx.x / CPB;
    const float* P = pos + (size_t)b * N * 3;
    int tid = threadIdx.x;
    int lane = tid & 31, wid = tid >> 5;
    int chunkBase = rank * (N / CPB);

    unsigned long long px2[PQ], py2[PQ], pz2[PQ];
    float dd[2*PQ];
#pragma unroll
    for (int q = 0; q < PQ; ++q) {
        int g0 = chunkBase + tid + (2*q)*NT, g1 = g0 + NT;
        px2[q] = f2pack(P[g0*3+0], P[g1*3+0]);
        py2[q] = f2pack(P[g0*3+1], P[g1*3+1]);
        pz2[q] = f2pack(P[g0*3+2], P[g1*3+2]);
        dd[2*q] = 1e10f; dd[2*q+1] = 1e10f;
    }

    __shared__ unsigned long long slots[2][CPB*16];  // (par, rank*16+wid)

    float cx = P[0], cy = P[1], cz = P[2];
    int far = 0;

    for (int it = 0; it < npoint; ++it) {
        int par = it & 1;
        if (rank == 0 && tid == 0) {
            outIdx[(size_t)b * npoint + it] = far;
            outPos[((size_t)b * npoint + it) * 3 + 0] = cx;
            outPos[((size_t)b * npoint + it) * 3 + 1] = cy;
            outPos[((size_t)b * npoint + it) * 3 + 2] = cz;
        }
        // sub realized as add of exact negation: bitwise == __fsub_rn
        unsigned long long ncx = f2pack(-cx, -cx);
        unsigned long long ncy = f2pack(-cy, -cy);
        unsigned long long ncz = f2pack(-cz, -cz);

        float bv; int bidx;
        // per-thread global indices ascend with q (i0 < i1): strict '>' keeps first max
#pragma unroll
        for (int q = 0; q < PQ; ++q) {
            unsigned long long dx = f2add(px2[q], ncx);
            unsigned long long dy = f2add(py2[q], ncy);
            unsigned long long dz = f2add(pz2[q], ncz);
            unsigned long long s  = f2add(f2add(f2mul(dx,dx), f2mul(dy,dy)), f2mul(dz,dz));
            float dlo, dhi; f2unpack(s, dlo, dhi);
            float n0 = fminf(dd[2*q],   dlo);
            float n1 = fminf(dd[2*q+1], dhi);
            dd[2*q] = n0; dd[2*q+1] = n1;
            int i0 = chunkBase + tid + (2*q)*NT, i1 = i0 + NT;
            float pv = (n1 > n0) ? n1 : n0;   // tie -> n0 (lower index)
            int   pi = (n1 > n0) ? i1 : i0;
            if (q == 0) { bv = pv; bidx = pi; }
            else if (pv > bv) { bv = pv; bidx = pi; }
        }
        // warp argmax via redux (monotone u32 compare for fp >= 0)
        unsigned ubv  = __float_as_uint(bv);
        unsigned wmax = __reduce_max_sync(0xffffffffu, ubv);
        int cand = (ubv == wmax) ? bidx : 0x7fffffff;
        int widx = __reduce_min_sync(0xffffffffu, cand);
        // lane0 of each warp broadcasts its partial to ALL cluster CTAs (DSMEM)
        if (lane == 0) {
            unsigned long long key = ((unsigned long long)wmax << 32) | (unsigned)widx;
            unsigned long long* mySlot = &slots[par][rank * 16 + wid];
#pragma unroll
            for (int r = 0; r < CPB; ++r) {
                unsigned long long* dst = cluster.map_shared_rank(mySlot, r);
                *dst = key;
            }
        }
        cluster.sync();
        // every CTA reduces the CPB*16 = 64 slots (2 per lane + redux pair)
        unsigned long long k1 = slots[par][lane];
        unsigned long long k2 = slots[par][lane + 32];
        unsigned v1 = (unsigned)(k1 >> 32), v2 = (unsigned)(k2 >> 32);
        int i1 = (int)(unsigned)k1, i2 = (int)(unsigned)k2;
        unsigned pv2; int pi2;
        if (v2 > v1 || (v2 == v1 && i2 < i1)) { pv2 = v2; pi2 = i2; }
        else                                  { pv2 = v1; pi2 = i1; }
        unsigned bmax = __reduce_max_sync(0xffffffffu, pv2);
        int c2 = (pv2 == bmax) ? pi2 : 0x7fffffff;
        far = __reduce_min_sync(0xffffffffu, c2);
        cx = P[far*3+0]; cy = P[far*3+1]; cz = P[far*3+2]; // L1-hit broadcast
    }
}

// ---------------- edge-conv phase A: Acat row = [x_i | mean nx | mean rel | mean d2] ----------------
__global__ void hbar_kernel(const float* __restrict__ xf, const float* __restrict__ pos,
                            const int* __restrict__ knn, int N, int C,
                            float* __restrict__ Acat, int ldA)
{
    int gw = (blockIdx.x * blockDim.x + threadIdx.x) >> 5;
    int lane = threadIdx.x & 31;
    if (gw >= BB * N) return;
    int b = gw / N, i = gw % N;
    const float* Pb = pos + (size_t)b * N * 3;
    const float* Xb = xf + (size_t)b * N * C;
    const int* nbr = knn + (size_t)gw * KNBR;

    int j = (lane < KNBR) ? nbr[lane] : 0;
    float rx = 0.f, ry = 0.f, rz = 0.f, d2 = 0.f;
    if (lane < KNBR) {
        float qx = Pb[i*3+0], qy = Pb[i*3+1], qz = Pb[i*3+2];
        rx = qx - Pb[j*3+0]; ry = qy - Pb[j*3+1]; rz = qz - Pb[j*3+2];
        d2 = (rx*rx + ry*ry) + rz*rz;
    }

    int jlist[KNBR];
#pragma unroll
    for (int kk = 0; kk < KNBR; ++kk)
        jlist[kk] = __shfl_sync(0xffffffffu, j, kk);

#pragma unroll
    for (int o = 16; o > 0; o >>= 1) {
        rx += __shfl_down_sync(0xffffffffu, rx, o);
        ry += __shfl_down_sync(0xffffffffu, ry, o);
        rz += __shfl_down_sync(0xffffffffu, rz, o);
        d2 += __shfl_down_sync(0xffffffffu, d2, o);
    }
    float* Arow = Acat + (size_t)gw * ldA;
    if (lane == 0) {
        const float inv = 1.0f / 16.0f;
        Arow[2*C + 0] = rx * inv;
        Arow[2*C + 1] = ry * inv;
        Arow[2*C + 2] = rz * inv;
        Arow[2*C + 3] = d2 * inv;
    }
    for (int c = lane; c < C; c += 32) {
        float acc = 0.f;
#pragma unroll
        for (int kk = 0; kk < KNBR; ++kk)
            acc += Xb[(size_t)jlist[kk] * C + c];
        Arow[c]     = Xb[(size_t)i * C + c];
        Arow[C + c] = acc * (1.0f / 16.0f);
    }
}

// ---------------- SGEMM v2: 128x64 tile, 8x4 per-thread, C = act(A@W + bias) ----------------
__global__ __launch_bounds__(256)
void sgemm_kernel(const float* __restrict__ A, int ldA,
                  const float* __restrict__ W,
                  const float* __restrict__ bias,
                  float* __restrict__ Cout,
                  int M, int N, int Kd, int act)
{
    __shared__ float As[16][128];
    __shared__ float Ws[16][64];
    int tid = threadIdx.x;
    int rowBase = blockIdx.y * 128, colBase = blockIdx.x * 64;
    int tx = tid & 15, ty = tid >> 4;
    int lm  = tid & 127;
    int lk8 = (tid >> 7) * 8;
    int wrow = tid >> 4, wcol4 = (tid & 15) * 4;
    float acc[8][4] = {};

    for (int k0 = 0; k0 < Kd; k0 += 16) {
        const float* Ap = A + (size_t)(rowBase + lm) * ldA + k0 + lk8;
#pragma unroll
        for (int q = 0; q < 8; ++q) {
            int k = k0 + lk8 + q;
            As[lk8 + q][lm] = (k < Kd) ? Ap[q] : 0.0f;
        }
        {
            int k = k0 + wrow;
#pragma unroll
            for (int q = 0; q < 4; ++q)
                Ws[wrow][wcol4 + q] = (k < Kd) ? W[(size_t)k * N + colBase + wcol4 + q] : 0.0f;
        }
        __syncthreads();
#pragma unroll
        for (int kk = 0; kk < 16; ++kk) {
            float4 a0 = *(const float4*)&As[kk][ty * 8];
            float4 a1 = *(const float4*)&As[kk][ty * 8 + 4];
            float4 wv = *(const float4*)&Ws[kk][tx * 4];
            float a[8] = {a0.x, a0.y, a0.z, a0.w, a1.x, a1.y, a1.z, a1.w};
            float w4[4] = {wv.x, wv.y, wv.z, wv.w};
#pragma unroll
            for (int q = 0; q < 8; ++q)
#pragma unroll
                for (int r = 0; r < 4; ++r)
                    acc[q][r] = fmaf(a[q], w4[r], acc[q][r]);
        }
        __syncthreads();
    }
#pragma unroll
    for (int q = 0; q < 8; ++q) {
        int m = rowBase + ty * 8 + q;
#pragma unroll
        for (int r = 0; r < 4; ++r) {
            int n = colBase + tx * 4 + r;
            float v = acc[q][r];
            if (bias) v += bias[n];
            if (act) v = (v >= 0.f) ? v : 0.2f * v;
            Cout[(size_t)m * N + n] = v;
        }
    }
}

// ---------------- gather: out[b,m,:] = src[b, idx[b,m], :] ----------------
__global__ void gather_kernel(const float* __restrict__ src, int C, int Nsrc,
                              const int* __restrict__ idx, int Mper, float* __restrict__ dst)
{
    int t = blockIdx.x * blockDim.x + threadIdx.x;
    int total = BB * Mper * C;
    if (t >= total) return;
    int c = t % C; int row = t / C; int b = row / Mper;
    dst[t] = src[((size_t)b * Nsrc + idx[row]) * C + c];
}

// ---------------- three_nn: top-3 + weights ----------------
__global__ void three_nn_kernel(const float* __restrict__ unk, int Nu,
                                const float* __restrict__ knw, int Nk,
                                int* __restrict__ outIdx, float* __restrict__ outW)
{
    const int TILE = 512;
    __shared__ float sx[512], sy[512], sz[512], sn[512];
    int b = blockIdx.y;
    const float* U = unk + (size_t)b * Nu * 3;
    const float* Kp = knw + (size_t)b * Nk * 3;
    int i = blockIdx.x * blockDim.x + threadIdx.x;

    float qx = U[i*3+0], qy = U[i*3+1], qz = U[i*3+2];
    float qn = __fadd_rn(__fadd_rn(__fmul_rn(qx,qx), __fmul_rn(qy,qy)), __fmul_rn(qz,qz));
    float b0 = 3e38f, b1 = 3e38f, b2 = 3e38f;
    int   i0 = -1, i1 = -1, i2 = -1;

    for (int j0 = 0; j0 < Nk; j0 += TILE) {
        for (int t = threadIdx.x; t < TILE; t += blockDim.x) {
            float x = Kp[(j0+t)*3+0], y = Kp[(j0+t)*3+1], z = Kp[(j0+t)*3+2];
            sx[t] = x; sy[t] = y; sz[t] = z;
            sn[t] = __fadd_rn(__fadd_rn(__fmul_rn(x,x), __fmul_rn(y,y)), __fmul_rn(z,z));
        }
        __syncthreads();
        for (int t = 0; t < TILE; ++t) {
            float dot = __fadd_rn(__fadd_rn(__fmul_rn(qx,sx[t]), __fmul_rn(qy,sy[t])), __fmul_rn(qz,sz[t]));
            float d = __fsub_rn(__fadd_rn(qn, sn[t]), __fmul_rn(2.0f, dot));
            int j = j0 + t;
            if (d < b2) {
                if (d < b0)      { b2 = b1; i2 = i1; b1 = b0; i1 = i0; b0 = d; i0 = j; }
                else if (d < b1) { b2 = b1; i2 = i1; b1 = d;  i1 = j; }
                else             { b2 = d;  i2 = j; }
            }
        }
        __syncthreads();
    }
    b0 = fmaxf(b0, 0.f); b1 = fmaxf(b1, 0.f); b2 = fmaxf(b2, 0.f);
    float r0 = 1.0f / (b0 + 1e-8f), r1 = 1.0f / (b1 + 1e-8f), r2 = 1.0f / (b2 + 1e-8f);
    float s = (r0 + r1) + r2;
    size_t o = ((size_t)b * Nu + i) * 3;
    outIdx[o+0] = i0; outIdx[o+1] = i1; outIdx[o+2] = i2;
    outW[o+0] = r0 / s; outW[o+1] = r1 / s; outW[o+2] = r2 / s;
}

// ---------------- three_interp into Acat columns ----------------
__global__ void interp_kernel(const float* __restrict__ feat, int C, int Nsrc,
                              const int* __restrict__ idx3, const float* __restrict__ w3,
                              int Mper, float* __restrict__ dst, int ldD, int colOff)
{
    int t = blockIdx.x * blockDim.x + threadIdx.x;
    int total = BB * Mper * C;
    if (t >= total) return;
    int c = t % C; int row = t / C; int b = row / Mper;
    const int* I = idx3 + (size_t)row * 3;
    const float* Wt = w3 + (size_t)row * 3;
    const float* F = feat + (size_t)b * Nsrc * C;
    float v = Wt[0] * F[(size_t)I[0] * C + c]
            + Wt[1] * F[(size_t)I[1] * C + c]
            + Wt[2] * F[(size_t)I[2] * C + c];
    dst[(size_t)row * ldD + colOff + c] = v;
}

// ---------------- strided column copy into Acat ----------------
__global__ void copy_cols_kernel(const float* __restrict__ src, int cols, int Mtot,
                                 float* __restrict__ dst, int ldD, int colOff)
{
    int t = blockIdx.x * blockDim.x + threadIdx.x;
    int total = Mtot * cols;
    if (t >= total) return;
    int c = t % cols; int row = t / cols;
    dst[(size_t)row * ldD + colOff + c] = src[t];
}

// ---------------- host orchestration ----------------
static inline void gemm_s(cudaStream_t s, const float* A, int ldA, const float* W,
                          const float* bias, float* C, int M, int N, int Kd, int act)
{
    dim3 grid(N / 64, M / 128);
    sgemm_kernel<<<grid, 256, 0, s>>>(A, ldA, W, bias, C, M, N, Kd, act);
}

extern "C" void kernel_launch(void* const* d_in, const int* in_sizes, int n_in,
                              void* d_out, int out_size)
{
    const float* x          = (const float*)d_in[0];
    const float* pos        = (const float*)d_in[1];
    const float* w_self0    = (const float*)d_in[2];
    const float* w_edge0    = (const float*)d_in[3];
    const float* w_self1    = (const float*)d_in[4];
    const float* w_edge1    = (const float*)d_in[5];
    const float* w_self2    = (const float*)d_in[6];
    const float* w_edge2    = (const float*)d_in[7];
    const float* w_up1      = (const float*)d_in[8];
    const float* b_up1      = (const float*)d_in[9];
    const float* w_upc1_self= (const float*)d_in[10];
    const float* w_upc1_edge= (const float*)d_in[11];
    const float* w_up0      = (const float*)d_in[12];
    const float* b_up0      = (const float*)d_in[13];
    const float* w_upc0_self= (const float*)d_in[14];
    const float* w_upc0_edge= (const float*)d_in[15];
    const float* w_out      = (const float*)d_in[16];
    const float* b_out      = (const float*)d_in[17];

    float* base = nullptr;
    cudaGetSymbolAddress((void**)&base, g_buf);

    int*   idx0  = (int*)(base + OFF_IDX0);
    int*   idx1  = (int*)(base + OFF_IDX1);
    int*   idx2  = (int*)(base + OFF_IDX2);
    int*   fps1  = (int*)(base + OFF_FPS1);
    int*   fps2  = (int*)(base + OFF_FPS2);
    float* pos1  = base + OFF_POS1;
    float* pos2  = base + OFF_POS2;
    float* feat0 = base + OFF_FEAT0;
    float* fg1   = base + OFF_FG1;
    float* feat1 = base + OFF_FEAT1;
    float* fg2   = base + OFF_FG2;
    float* feat2 = base + OFF_FEAT2;
    int*   nni1  = (int*)(base + OFF_NNI1);
    float* nnw1  = base + OFF_NNW1;
    int*   nni0  = (int*)(base + OFF_NNI0);
    float* nnw0  = base + OFF_NNW0;
    float* fu1p  = base + OFF_FU1P;
    float* fu1   = base + OFF_FU1;
    float* fu0   = base + OFF_FU0;
    float* fout  = base + OFF_FOUT;
    float* Acat  = base + OFF_ACAT;
    float* Wcat  = base + OFF_WCAT;

    static cudaStream_t sA = [](){ cudaStream_t s; cudaStreamCreateWithFlags(&s, cudaStreamNonBlocking); return s; }();
    static cudaStream_t sB = [](){ cudaStream_t s; cudaStreamCreateWithFlags(&s, cudaStreamNonBlocking); return s; }();
    static cudaEvent_t ev0   = [](){ cudaEvent_t e; cudaEventCreateWithFlags(&e, cudaEventDisableTiming); return e; }();
    static cudaEvent_t evF1  = [](){ cudaEvent_t e; cudaEventCreateWithFlags(&e, cudaEventDisableTiming); return e; }();
    static cudaEvent_t evF2  = [](){ cudaEvent_t e; cudaEventCreateWithFlags(&e, cudaEventDisableTiming); return e; }();
    static cudaEvent_t evT0  = [](){ cudaEvent_t e; cudaEventCreateWithFlags(&e, cudaEventDisableTiming); return e; }();
    static cudaEvent_t evT1  = [](){ cudaEvent_t e; cudaEventCreateWithFlags(&e, cudaEventDisableTiming); return e; }();

    cudaStream_t s0 = 0;

    // ---- fork: FPS chain (cluster-parallel) on side stream A ----
    cudaEventRecord(ev0, s0);
    cudaStreamWaitEvent(sA, ev0, 0);
    cudaStreamWaitEvent(sB, ev0, 0);
    fps6_kernel<2, 4><<<BB*4, 512, 0, sA>>>(pos, N0, N1, fps1, pos1);   // 8192 -> 4096
    cudaEventRecord(evF1, sA);
    fps6_kernel<1, 4><<<BB*4, 512, 0, sA>>>(pos1, N1, N2, fps2, pos2);  // 4096 -> 2048
    cudaEventRecord(evF2, sA);

    // ---- three_nn kernels on side stream B (overlap GEMM chains) ----
    cudaStreamWaitEvent(sB, evF1, 0);
    three_nn_kernel<<<dim3(N0/128, BB), 128, 0, sB>>>(pos, N0, pos1, N1, nni0, nnw0);
    cudaEventRecord(evT0, sB);
    cudaStreamWaitEvent(sB, evF2, 0);
    three_nn_kernel<<<dim3(N1/128, BB), 128, 0, sB>>>(pos1, N1, pos2, N2, nni1, nnw1);
    cudaEventRecord(evT1, sB);

    // ---- level 0 edge conv (concurrent with fps1): C=4, Kcat=12, N=64 ----
    knn_kernel<<<dim3(N0/128, BB), 128, 0, s0>>>(pos, N0, idx0);
    hbar_kernel<<<(BB*N0)/4, 128, 0, s0>>>(x, pos, idx0, N0, 4, Acat, 12);
    cudaMemcpyAsync(Wcat,         w_self0, (size_t)4*64*4, cudaMemcpyDeviceToDevice, s0);
    cudaMemcpyAsync(Wcat + 4*64,  w_edge0, (size_t)8*64*4, cudaMemcpyDeviceToDevice, s0);
    gemm_s(s0, Acat, 12, Wcat, nullptr, feat0, BB*N0, 64, 12, 1);

    // ---- join fps1; level 1 chain (concurrent with fps2) ----
    cudaStreamWaitEvent(s0, evF1, 0);
    gather_kernel<<<(BB*N1*64 + 255)/256, 256, 0, s0>>>(feat0, 64, N0, fps1, N1, fg1);
    knn_kernel<<<dim3(N1/128, BB), 128, 0, s0>>>(pos1, N1, idx1);
    hbar_kernel<<<(BB*N1)/4, 128, 0, s0>>>(fg1, pos1, idx1, N1, 64, Acat, 132);
    cudaMemcpyAsync(Wcat,          w_self1, (size_t)64*128*4, cudaMemcpyDeviceToDevice, s0);
    cudaMemcpyAsync(Wcat + 64*128, w_edge1, (size_t)68*128*4, cudaMemcpyDeviceToDevice, s0);
    gemm_s(s0, Acat, 132, Wcat, nullptr, feat1, BB*N1, 128, 132, 1);

    // ---- join fps2; level 2 edge conv: C=128, Kcat=260, N=256 ----
    cudaStreamWaitEvent(s0, evF2, 0);
    gather_kernel<<<(BB*N2*128 + 255)/256, 256, 0, s0>>>(feat1, 128, N1, fps2, N2, fg2);
    knn_kernel<<<dim3(N2/128, BB), 128, 0, s0>>>(pos2, N2, idx2);
    hbar_kernel<<<(BB*N2)/4, 128, 0, s0>>>(fg2, pos2, idx2, N2, 128, Acat, 260);
    cudaMemcpyAsync(Wcat,           w_self2, (size_t)128*256*4, cudaMemcpyDeviceToDevice, s0);
    cudaMemcpyAsync(Wcat + 128*256, w_edge2, (size_t)132*256*4, cudaMemcpyDeviceToDevice, s0);
    gemm_s(s0, Acat, 260, Wcat, nullptr, feat2, BB*N2, 256, 260, 1);

    // ---- up 1: interp feat2, cat feat1, linear ----
    cudaStreamWaitEvent(s0, evT1, 0);
    interp_kernel<<<(BB*N1*256 + 255)/256, 256, 0, s0>>>(feat2, 256, N2, nni1, nnw1, N1, Acat, 384, 0);
    copy_cols_kernel<<<(BB*N1*128 + 255)/256, 256, 0, s0>>>(feat1, 128, BB*N1, Acat, 384, 256);
    gemm_s(s0, Acat, 384, w_up1, b_up1, fu1p, BB*N1, 128, 384, 1);

    // ---- up 1 edge conv (reuse idx1): C=128, Kcat=260, N=128 ----
    hbar_kernel<<<(BB*N1)/4, 128, 0, s0>>>(fu1p, pos1, idx1, N1, 128, Acat, 260);
    cudaMemcpyAsync(Wcat,           w_upc1_self, (size_t)128*128*4, cudaMemcpyDeviceToDevice, s0);
    cudaMemcpyAsync(Wcat + 128*128, w_upc1_edge, (size_t)132*128*4, cudaMemcpyDeviceToDevice, s0);
    gemm_s(s0, Acat, 260, Wcat, nullptr, fu1, BB*N1, 128, 260, 1);

    // ---- up 0: interp fu1, cat feat0, linear ----
    cudaStreamWaitEvent(s0, evT0, 0);
    interp_kernel<<<(BB*N0*128 + 255)/256, 256, 0, s0>>>(fu1, 128, N1, nni0, nnw0, N0, Acat, 192, 0);
    copy_cols_kernel<<<(BB*N0*64 + 255)/256, 256, 0, s0>>>(feat0, 64, BB*N0, Acat, 192, 128);
    gemm_s(s0, Acat, 192, w_up0, b_up0, fu0, BB*N0, 64, 192, 1);

    // ---- up 0 edge conv (reuse idx0): C=64, Kcat=132, N=64 ----
    hbar_kernel<<<(BB*N0)/4, 128, 0, s0>>>(fu0, pos, idx0, N0, 64, Acat, 132);
    cudaMemcpyAsync(Wcat,         w_upc0_self, (size_t)64*64*4, cudaMemcpyDeviceToDevice, s0);
    cudaMemcpyAsync(Wcat + 64*64, w_upc0_edge, (size_t)68*64*4, cudaMemcpyDeviceToDevice, s0);
    gemm_s(s0, Acat, 132, Wcat, nullptr, fout, BB*N0, 64, 132, 1);

    // ---- output projection: no activation ----
    gemm_s(s0, fout, 64, w_out, b_out, (float*)d_out, BB*N0, 128, 64, 0);
}

// round 9
// speedup vs baseline: 1.8541x; 1.8541x over previous
#include <cuda_runtime.h>
#include <cstdint>

// ---------------- problem constants ----------------
#define BB 2
#define N0 8192
#define N1 4096
#define N2 2048
#define KNBR 16

// ---------------- one big scratch buffer (no allocs allowed) ----------------
__device__ float g_buf[16 * 1024 * 1024]; // 64 MB

#define ALIGN256(x) (((x) + 255) & ~255)
static const size_t OFF_IDX0  = 0;
static const size_t OFF_IDX1  = ALIGN256(OFF_IDX0  + 2*8192*16);
static const size_t OFF_IDX2  = ALIGN256(OFF_IDX1  + 2*4096*16);
static const size_t OFF_FPS1  = ALIGN256(OFF_IDX2  + 2*2048*16);
static const size_t OFF_FPS2  = ALIGN256(OFF_FPS1  + 2*4096);
static const size_t OFF_POS1  = ALIGN256(OFF_FPS2  + 2*2048);
static const size_t OFF_POS2  = ALIGN256(OFF_POS1  + 2*4096*3);
static const size_t OFF_FEAT0 = ALIGN256(OFF_POS2  + 2*2048*3);
static const size_t OFF_FG1   = ALIGN256(OFF_FEAT0 + 2*8192*64);
static const size_t OFF_FEAT1 = ALIGN256(OFF_FG1   + 2*4096*64);
static const size_t OFF_FG2   = ALIGN256(OFF_FEAT1 + 2*4096*128);
static const size_t OFF_FEAT2 = ALIGN256(OFF_FG2   + 2*2048*128);
static const size_t OFF_NNI1  = ALIGN256(OFF_FEAT2 + 2*2048*256);
static const size_t OFF_NNW1  = ALIGN256(OFF_NNI1  + 2*4096*3);
static const size_t OFF_NNI0  = ALIGN256(OFF_NNW1  + 2*4096*3);
static const size_t OFF_NNW0  = ALIGN256(OFF_NNI0  + 2*8192*3);
static const size_t OFF_FU1P  = ALIGN256(OFF_NNW0  + 2*8192*3);
static const size_t OFF_FU1   = ALIGN256(OFF_FU1P  + 2*4096*128);
static const size_t OFF_FU0   = ALIGN256(OFF_FU1   + 2*4096*128);
static const size_t OFF_FOUT  = ALIGN256(OFF_FU0   + 2*8192*64);
static const size_t OFF_ACAT  = ALIGN256(OFF_FOUT  + 2*8192*64);
static const size_t OFF_WCAT  = ALIGN256(OFF_ACAT  + (size_t)16384*384);
static const size_t OFF_PS0   = ALIGN256(OFF_WCAT  + 384*256);       // sorted pos0: 2*8192*3
static const size_t OFF_PM0   = ALIGN256(OFF_PS0   + 2*8192*3);      // perm0: 2*8192 ints
static const size_t OFF_BB0   = ALIGN256(OFF_PM0   + 2*8192);        // tile bboxes: 2*16*6
static const size_t OFF_PS1   = ALIGN256(OFF_BB0   + 2*96);          // sorted pos1: 2*4096*3
static const size_t OFF_PM1   = ALIGN256(OFF_PS1   + 2*4096*3);      // perm1: 2*4096 ints
static const size_t OFF_BB1   = ALIGN256(OFF_PM1   + 2*4096);        // 2*16*6

// ---------------- packed f32x2 helpers (exact IEEE RN per lane) ----------------
__device__ __forceinline__ unsigned long long f2pack(float lo, float hi) {
    unsigned long long r;
    asm("mov.b64 %0, {%1, %2};" : "=l"(r) : "f"(lo), "f"(hi));
    return r;
}
__device__ __forceinline__ void f2unpack(unsigned long long v, float& lo, float& hi) {
    asm("mov.b64 {%0, %1}, %2;" : "=f"(lo), "=f"(hi) : "l"(v));
}
__device__ __forceinline__ unsigned long long f2add(unsigned long long a, unsigned long long b) {
    unsigned long long r;
    asm("add.rn.f32x2 %0, %1, %2;" : "=l"(r) : "l"(a), "l"(b));
    return r;
}
__device__ __forceinline__ unsigned long long f2mul(unsigned long long a, unsigned long long b) {
    unsigned long long r;
    asm("mul.rn.f32x2 %0, %1, %2;" : "=l"(r) : "l"(a), "l"(b));
    return r;
}

// ---------------- KNN: brute force, top-16 register insertion ----------------
__global__ void knn_kernel(const float* __restrict__ pos, int N, int* __restrict__ outIdx)
{
    const int TILE = 512;
    __shared__ float sx[512], sy[512], sz[512], sn[512];
    int b = blockIdx.y;
    const float* P = pos + (size_t)b * N * 3;
    int i = blockIdx.x * blockDim.x + threadIdx.x;

    float qx = P[i*3+0], qy = P[i*3+1], qz = P[i*3+2];
    float qn = __fadd_rn(__fadd_rn(__fmul_rn(qx,qx), __fmul_rn(qy,qy)), __fmul_rn(qz,qz));

    float bd[KNBR]; int bi[KNBR];
#pragma unroll
    for (int t = 0; t < KNBR; ++t) { bd[t] = 3.0e38f; bi[t] = -1; }

    for (int j0 = 0; j0 < N; j0 += TILE) {
        for (int t = threadIdx.x; t < TILE; t += blockDim.x) {
            float x = P[(j0+t)*3+0], y = P[(j0+t)*3+1], z = P[(j0+t)*3+2];
            sx[t] = x; sy[t] = y; sz[t] = z;
            sn[t] = __fadd_rn(__fadd_rn(__fmul_rn(x,x), __fmul_rn(y,y)), __fmul_rn(z,z));
        }
        __syncthreads();
        for (int t = 0; t < TILE; ++t) {
            float dot = __fadd_rn(__fadd_rn(__fmul_rn(qx,sx[t]), __fmul_rn(qy,sy[t])), __fmul_rn(qz,sz[t]));
            float d = __fsub_rn(__fadd_rn(qn, sn[t]), __fmul_rn(2.0f, dot));
            if (d < bd[KNBR-1]) {
                bd[KNBR-1] = d; bi[KNBR-1] = j0 + t;
#pragma unroll
                for (int s = KNBR-1; s > 0; --s) {
                    if (bd[s] < bd[s-1]) {
                        float tv = bd[s]; bd[s] = bd[s-1]; bd[s-1] = tv;
                        int ti = bi[s]; bi[s] = bi[s-1]; bi[s-1] = ti;
                    }
                }
            }
        }
        __syncthreads();
    }
    int* O = outIdx + ((size_t)b * N + i) * KNBR;
#pragma unroll
    for (int t = 0; t < KNBR; ++t) O[t] = bi[t];
}

// ---------------- Morton binning: sort points into 16 spatial tiles ----------------
// Output: psort [N,3] (positions in sorted order), perm [N] (orig idx per slot),
// tileBB [16*6] (xmin,xmax,ymin,ymax,zmin,zmax per tile of N/16 consecutive slots).
__device__ __forceinline__ unsigned expand3(unsigned v) {
    return (v & 1u) | ((v & 2u) << 2) | ((v & 4u) << 4);
}
template<int N, int PPT>   // PPT = N/512
__global__ __launch_bounds__(512, 1)
void morton_kernel(const float* __restrict__ pos, float* __restrict__ psort,
                   int* __restrict__ perm, float* __restrict__ tileBB)
{
    int b = blockIdx.x;
    const float* P = pos + (size_t)b * N * 3;
    float* PS = psort + (size_t)b * N * 3;
    int* PM = perm + (size_t)b * N;
    float* BBo = tileBB + (size_t)b * 96;
    int tid = threadIdx.x, lane = tid & 31, wid = tid >> 5;

    // ---- 1. batch bbox ----
    float mnx = 3e38f, mny = 3e38f, mnz = 3e38f;
    float mxx = -3e38f, mxy = -3e38f, mxz = -3e38f;
    float xs[PPT], ys[PPT], zs[PPT];
#pragma unroll
    for (int k = 0; k < PPT; ++k) {
        int i = tid + k * 512;
        float x = P[i*3+0], y = P[i*3+1], z = P[i*3+2];
        xs[k] = x; ys[k] = y; zs[k] = z;
        mnx = fminf(mnx, x); mxx = fmaxf(mxx, x);
        mny = fminf(mny, y); mxy = fmaxf(mxy, y);
        mnz = fminf(mnz, z); mxz = fmaxf(mxz, z);
    }
#pragma unroll
    for (int o = 16; o > 0; o >>= 1) {
        mnx = fminf(mnx, __shfl_xor_sync(0xffffffffu, mnx, o));
        mxx = fmaxf(mxx, __shfl_xor_sync(0xffffffffu, mxx, o));
        mny = fminf(mny, __shfl_xor_sync(0xffffffffu, mny, o));
        mxy = fmaxf(mxy, __shfl_xor_sync(0xffffffffu, mxy, o));
        mnz = fminf(mnz, __shfl_xor_sync(0xffffffffu, mnz, o));
        mxz = fmaxf(mxz, __shfl_xor_sync(0xffffffffu, mxz, o));
    }
    __shared__ float sb[16][6];
    __shared__ float gb[6];
    if (lane == 0) {
        sb[wid][0] = mnx; sb[wid][1] = mxx; sb[wid][2] = mny;
        sb[wid][3] = mxy; sb[wid][4] = mnz; sb[wid][5] = mxz;
    }
    __syncthreads();
    if (tid < 32) {
        float a0 = (lane < 16) ? sb[lane][0] : 3e38f;
        float a1 = (lane < 16) ? sb[lane][1] : -3e38f;
        float a2 = (lane < 16) ? sb[lane][2] : 3e38f;
        float a3 = (lane < 16) ? sb[lane][3] : -3e38f;
        float a4 = (lane < 16) ? sb[lane][4] : 3e38f;
        float a5 = (lane < 16) ? sb[lane][5] : -3e38f;
#pragma unroll
        for (int o = 8; o > 0; o >>= 1) {
            a0 = fminf(a0, __shfl_xor_sync(0xffffffffu, a0, o));
            a1 = fmaxf(a1, __shfl_xor_sync(0xffffffffu, a1, o));
            a2 = fminf(a2, __shfl_xor_sync(0xffffffffu, a2, o));
            a3 = fmaxf(a3, __shfl_xor_sync(0xffffffffu, a3, o));
            a4 = fminf(a4, __shfl_xor_sync(0xffffffffu, a4, o));
            a5 = fmaxf(a5, __shfl_xor_sync(0xffffffffu, a5, o));
        }
        if (lane == 0) { gb[0]=a0; gb[1]=a1; gb[2]=a2; gb[3]=a3; gb[4]=a4; gb[5]=a5; }
    }
    __syncthreads();
    float bx = gb[0], rx = 8.0f / fmaxf(gb[1] - gb[0], 1e-20f);
    float by = gb[2], ry = 8.0f / fmaxf(gb[3] - gb[2], 1e-20f);
    float bz = gb[4], rz = 8.0f / fmaxf(gb[5] - gb[4], 1e-20f);

    // ---- 2. bins + histogram ----
    __shared__ int hist[512];
    __shared__ int scan[512];
    __shared__ int cursor[512];
    hist[tid] = 0;
    __syncthreads();
    int bins[PPT];
#pragma unroll
    for (int k = 0; k < PPT; ++k) {
        int xi = min(7, max(0, (int)((xs[k] - bx) * rx)));
        int yi = min(7, max(0, (int)((ys[k] - by) * ry)));
        int zi = min(7, max(0, (int)((zs[k] - bz) * rz)));
        bins[k] = (int)(expand3(xi) | (expand3(yi) << 1) | (expand3(zi) << 2));
        atomicAdd(&hist[bins[k]], 1);
    }
    __syncthreads();
    // ---- 3. inclusive scan -> exclusive starts ----
    scan[tid] = hist[tid];
    __syncthreads();
    for (int off = 1; off < 512; off <<= 1) {
        int v = (tid >= off) ? scan[tid - off] : 0;
        __syncthreads();
        scan[tid] += v;
        __syncthreads();
    }
    cursor[tid] = scan[tid] - hist[tid];
    __syncthreads();
    // ---- 4. scatter ----
#pragma unroll
    for (int k = 0; k < PPT; ++k) {
        int i = tid + k * 512;
        int slot = atomicAdd(&cursor[bins[k]], 1);
        PS[slot*3+0] = xs[k]; PS[slot*3+1] = ys[k]; PS[slot*3+2] = zs[k];
        PM[slot] = i;
    }
    __syncthreads();
    // ---- 5. per-tile bboxes (tile = N/16 consecutive slots, warp w -> tile w) ----
    {
        const int TS = N / 16;
        float tnx = 3e38f, tny = 3e38f, tnz = 3e38f;
        float txx = -3e38f, txy = -3e38f, txz = -3e38f;
        for (int k = lane; k < TS; k += 32) {
            int s = wid * TS + k;
            float x = PS[s*3+0], y = PS[s*3+1], z = PS[s*3+2];
            tnx = fminf(tnx, x); txx = fmaxf(txx, x);
            tny = fminf(tny, y); txy = fmaxf(txy, y);
            tnz = fminf(tnz, z); txz = fmaxf(txz, z);
        }
#pragma unroll
        for (int o = 16; o > 0; o >>= 1) {
            tnx = fminf(tnx, __shfl_xor_sync(0xffffffffu, tnx, o));
            txx = fmaxf(txx, __shfl_xor_sync(0xffffffffu, txx, o));
            tny = fminf(tny, __shfl_xor_sync(0xffffffffu, tny, o));
            txy = fmaxf(txy, __shfl_xor_sync(0xffffffffu, txy, o));
            tnz = fminf(tnz, __shfl_xor_sync(0xffffffffu, tnz, o));
            txz = fmaxf(txz, __shfl_xor_sync(0xffffffffu, txz, o));
        }
        if (lane == 0) {
            BBo[wid*6+0] = tnx; BBo[wid*6+1] = txx;
            BBo[wid*6+2] = tny; BBo[wid*6+3] = txy;
            BBo[wid*6+4] = tnz; BBo[wid*6+5] = txz;
        }
    }
}

// ---------------- FPS v8: tile-pruned exact FPS (tile = warp) ----------------
// dd values and selections bitwise identical to unpruned version: pruning only
// skips provably no-op min-updates; ties broken on ORIGINAL index everywhere.
template<int PQ>  // pts/thread = 2*PQ; tile = 64*PQ pts; N = 1024*PQ
__global__ __launch_bounds__(512, 1)
void fps8_kernel(const float* __restrict__ posOrig,
                 const float* __restrict__ psort, const int* __restrict__ perm,
                 const float* __restrict__ tileBB,
                 int N, int npoint, int* __restrict__ outIdx, float* __restrict__ outPos)
{
    int b = blockIdx.x;
    const float* P  = posOrig + (size_t)b * N * 3;   // centroid fetch by orig idx
    const float* PS = psort   + (size_t)b * N * 3;
    const int*   PM = perm    + (size_t)b * N;
    const float* BBt = tileBB + (size_t)b * 96;
    int tid = threadIdx.x, lane = tid & 31, wid = tid >> 5;
    const int tileBase = wid * 64 * PQ;

    unsigned long long px2[PQ], py2[PQ], pz2[PQ];
    unsigned dd[2*PQ];
    int oidx[2*PQ];
#pragma unroll
    for (int q = 0; q < PQ; ++q) {
        int s0 = tileBase + lane + (2*q)*32, s1 = s0 + 32;
        px2[q] = f2pack(PS[s0*3+0], PS[s1*3+0]);
        py2[q] = f2pack(PS[s0*3+1], PS[s1*3+1]);
        pz2[q] = f2pack(PS[s0*3+2], PS[s1*3+2]);
        dd[2*q]   = __float_as_uint(1e10f);
        dd[2*q+1] = __float_as_uint(1e10f);
        oidx[2*q]   = PM[s0];
        oidx[2*q+1] = PM[s1];
    }
    float bxn = BBt[wid*6+0], bxx = BBt[wid*6+1];
    float byn = BBt[wid*6+2], byx = BBt[wid*6+3];
    float bzn = BBt[wid*6+4], bzx = BBt[wid*6+5];

    __shared__ unsigned swv[2][16];
    __shared__ int      swi[2][16];

    unsigned tmax = __float_as_uint(1e10f);
    int targ = 0x7fffffff;
    float cx = P[0], cy = P[1], cz = P[2];
    int far = 0;

    for (int it = 0; it < npoint; ++it) {
        int par = it & 1;
        if (tid == 0) {
            outIdx[(size_t)b * npoint + it] = far;
            outPos[((size_t)b * npoint + it) * 3 + 0] = cx;
            outPos[((size_t)b * npoint + it) * 3 + 1] = cy;
            outPos[((size_t)b * npoint + it) * 3 + 2] = cz;
        }
        // ---- prune check (warp-uniform) ----
        float dxl = fmaxf(fmaxf(bxn - cx, cx - bxx), 0.0f);
        float dyl = fmaxf(fmaxf(byn - cy, cy - byx), 0.0f);
        float dzl = fmaxf(fmaxf(bzn - cz, cz - bzx), 0.0f);
        float lb  = (dxl*dxl + dyl*dyl) + dzl*dzl;
        bool skip = (lb * 0.99999f) > __uint_as_float(tmax);

        if (!skip) {
            unsigned long long ncx = f2pack(-cx, -cx);
            unsigned long long ncy = f2pack(-cy, -cy);
            unsigned long long ncz = f2pack(-cz, -cz);
            unsigned mm = 0u;
#pragma unroll
            for (int q = 0; q < PQ; ++q) {
                unsigned long long dx = f2add(px2[q], ncx);
                unsigned long long dy = f2add(py2[q], ncy);
                unsigned long long dz = f2add(pz2[q], ncz);
                unsigned long long s  = f2add(f2add(f2mul(dx,dx), f2mul(dy,dy)), f2mul(dz,dz));
                float flo, fhi; f2unpack(s, flo, fhi);
                // nonneg floats: u32 min == fminf bitwise (ALU pipe)
                unsigned nlo = min(dd[2*q],   __float_as_uint(flo));
                unsigned nhi = min(dd[2*q+1], __float_as_uint(fhi));
                dd[2*q] = nlo; dd[2*q+1] = nhi;
                mm = max(mm, max(nlo, nhi));
            }
            tmax = __reduce_max_sync(0xffffffffu, mm);
            // find smallest ORIGINAL index among dd == tmax
            int cand = 0x7fffffff;
#pragma unroll
            for (int j = 0; j < 2*PQ; ++j)
                if (dd[j] == tmax) cand = min(cand, oidx[j]);
            targ = __reduce_min_sync(0xffffffffu, cand);
        }
        if (lane == 0) { swv[par][wid] = tmax; swi[par][wid] = targ; }
        __syncthreads();
        // block reduce over 16 tile slots (every warp; single barrier/iter)
        unsigned v  = (lane < 16) ? swv[par][lane] : 0u;
        int      ix = swi[par][lane & 15];
        unsigned bmax = __reduce_max_sync(0xffffffffu, v);
        int c2 = (v == bmax && lane < 16) ? ix : 0x7fffffff;
        far = __reduce_min_sync(0xffffffffu, c2);
        cx = P[far*3+0]; cy = P[far*3+1]; cz = P[far*3+2];
    }
}

// ---------------- edge-conv phase A ----------------
__global__ void hbar_kernel(const float* __restrict__ xf, const float* __restrict__ pos,
                            const int* __restrict__ knn, int N, int C,
                            float* __restrict__ Acat, int ldA)
{
    int gw = (blockIdx.x * blockDim.x + threadIdx.x) >> 5;
    int lane = threadIdx.x & 31;
    if (gw >= BB * N) return;
    int b = gw / N, i = gw % N;
    const float* Pb = pos + (size_t)b * N * 3;
    const float* Xb = xf + (size_t)b * N * C;
    const int* nbr = knn + (size_t)gw * KNBR;

    int j = (lane < KNBR) ? nbr[lane] : 0;
    float rx = 0.f, ry = 0.f, rz = 0.f, d2 = 0.f;
    if (lane < KNBR) {
        float qx = Pb[i*3+0], qy = Pb[i*3+1], qz = Pb[i*3+2];
        rx = qx - Pb[j*3+0]; ry = qy - Pb[j*3+1]; rz = qz - Pb[j*3+2];
        d2 = (rx*rx + ry*ry) + rz*rz;
    }

    int jlist[KNBR];
#pragma unroll
    for (int kk = 0; kk < KNBR; ++kk)
        jlist[kk] = __shfl_sync(0xffffffffu, j, kk);

#pragma unroll
    for (int o = 16; o > 0; o >>= 1) {
        rx += __shfl_down_sync(0xffffffffu, rx, o);
        ry += __shfl_down_sync(0xffffffffu, ry, o);
        rz += __shfl_down_sync(0xffffffffu, rz, o);
        d2 += __shfl_down_sync(0xffffffffu, d2, o);
    }
    float* Arow = Acat + (size_t)gw * ldA;
    if (lane == 0) {
        const float inv = 1.0f / 16.0f;
        Arow[2*C + 0] = rx * inv;
        Arow[2*C + 1] = ry * inv;
        Arow[2*C + 2] = rz * inv;
        Arow[2*C + 3] = d2 * inv;
    }
    for (int c = lane; c < C; c += 32) {
        float acc = 0.f;
#pragma unroll
        for (int kk = 0; kk < KNBR; ++kk)
            acc += Xb[(size_t)jlist[kk] * C + c];
        Arow[c]     = Xb[(size_t)i * C + c];
        Arow[C + c] = acc * (1.0f / 16.0f);
    }
}

// ---------------- SGEMM: 128x64 tile, 8x4 per-thread ----------------
__global__ __launch_bounds__(256)
void sgemm_kernel(const float* __restrict__ A, int ldA,
                  const float* __restrict__ W,
                  const float* __restrict__ bias,
                  float* __restrict__ Cout,
                  int M, int N, int Kd, int act)
{
    __shared__ float As[16][128];
    __shared__ float Ws[16][64];
    int tid = threadIdx.x;
    int rowBase = blockIdx.y * 128, colBase = blockIdx.x * 64;
    int tx = tid & 15, ty = tid >> 4;
    int lm  = tid & 127;
    int lk8 = (tid >> 7) * 8;
    int wrow = tid >> 4, wcol4 = (tid & 15) * 4;
    float acc[8][4] = {};

    for (int k0 = 0; k0 < Kd; k0 += 16) {
        const float* Ap = A + (size_t)(rowBase + lm) * ldA + k0 + lk8;
#pragma unroll
        for (int q = 0; q < 8; ++q) {
            int k = k0 + lk8 + q;
            As[lk8 + q][lm] = (k < Kd) ? Ap[q] : 0.0f;
        }
        {
            int k = k0 + wrow;
#pragma unroll
            for (int q = 0; q < 4; ++q)
                Ws[wrow][wcol4 + q] = (k < Kd) ? W[(size_t)k * N + colBase + wcol4 + q] : 0.0f;
        }
        __syncthreads();
#pragma unroll
        for (int kk = 0; kk < 16; ++kk) {
            float4 a0 = *(const float4*)&As[kk][ty * 8];
            float4 a1 = *(const float4*)&As[kk][ty * 8 + 4];
            float4 wv = *(const float4*)&Ws[kk][tx * 4];
            float a[8] = {a0.x, a0.y, a0.z, a0.w, a1.x, a1.y, a1.z, a1.w};
            float w4[4] = {wv.x, wv.y, wv.z, wv.w};
#pragma unroll
            for (int q = 0; q < 8; ++q)
#pragma unroll
                for (int r = 0; r < 4; ++r)
                    acc[q][r] = fmaf(a[q], w4[r], acc[q][r]);
        }
        __syncthreads();
    }
#pragma unroll
    for (int q = 0; q < 8; ++q) {
        int m = rowBase + ty * 8 + q;
#pragma unroll
        for (int r = 0; r < 4; ++r) {
            int n = colBase + tx * 4 + r;
            float v = acc[q][r];
            if (bias) v += bias[n];
            if (act) v = (v >= 0.f) ? v : 0.2f * v;
            Cout[(size_t)m * N + n] = v;
        }
    }
}

// ---------------- gather ----------------
__global__ void gather_kernel(const float* __restrict__ src, int C, int Nsrc,
                              const int* __restrict__ idx, int Mper, float* __restrict__ dst)
{
    int t = blockIdx.x * blockDim.x + threadIdx.x;
    int total = BB * Mper * C;
    if (t >= total) return;
    int c = t % C; int row = t / C; int b = row / Mper;
    dst[t] = src[((size_t)b * Nsrc + idx[row]) * C + c];
}

// ---------------- three_nn ----------------
__global__ void three_nn_kernel(const float* __restrict__ unk, int Nu,
                                const float* __restrict__ knw, int Nk,
                                int* __restrict__ outIdx, float* __restrict__ outW)
{
    const int TILE = 512;
    __shared__ float sx[512], sy[512], sz[512], sn[512];
    int b = blockIdx.y;
    const float* U = unk + (size_t)b * Nu * 3;
    const float* Kp = knw + (size_t)b * Nk * 3;
    int i = blockIdx.x * blockDim.x + threadIdx.x;

    float qx = U[i*3+0], qy = U[i*3+1], qz = U[i*3+2];
    float qn = __fadd_rn(__fadd_rn(__fmul_rn(qx,qx), __fmul_rn(qy,qy)), __fmul_rn(qz,qz));
    float b0 = 3e38f, b1 = 3e38f, b2 = 3e38f;
    int   i0 = -1, i1 = -1, i2 = -1;

    for (int j0 = 0; j0 < Nk; j0 += TILE) {
        for (int t = threadIdx.x; t < TILE; t += blockDim.x) {
            float x = Kp[(j0+t)*3+0], y = Kp[(j0+t)*3+1], z = Kp[(j0+t)*3+2];
            sx[t] = x; sy[t] = y; sz[t] = z;
            sn[t] = __fadd_rn(__fadd_rn(__fmul_rn(x,x), __fmul_rn(y,y)), __fmul_rn(z,z));
        }
        __syncthreads();
        for (int t = 0; t < TILE; ++t) {
            float dot = __fadd_rn(__fadd_rn(__fmul_rn(qx,sx[t]), __fmul_rn(qy,sy[t])), __fmul_rn(qz,sz[t]));
            float d = __fsub_rn(__fadd_rn(qn, sn[t]), __fmul_rn(2.0f, dot));
            int j = j0 + t;
            if (d < b2) {
                if (d < b0)      { b2 = b1; i2 = i1; b1 = b0; i1 = i0; b0 = d; i0 = j; }
                else if (d < b1) { b2 = b1; i2 = i1; b1 = d;  i1 = j; }
                else             { b2 = d;  i2 = j; }
            }
        }
        __syncthreads();
    }
    b0 = fmaxf(b0, 0.f); b1 = fmaxf(b1, 0.f); b2 = fmaxf(b2, 0.f);
    float r0 = 1.0f / (b0 + 1e-8f), r1 = 1.0f / (b1 + 1e-8f), r2 = 1.0f / (b2 + 1e-8f);
    float s = (r0 + r1) + r2;
    size_t o = ((size_t)b * Nu + i) * 3;
    outIdx[o+0] = i0; outIdx[o+1] = i1; outIdx[o+2] = i2;
    outW[o+0] = r0 / s; outW[o+1] = r1 / s; outW[o+2] = r2 / s;
}

// ---------------- three_interp into Acat columns ----------------
__global__ void interp_kernel(const float* __restrict__ feat, int C, int Nsrc,
                              const int* __restrict__ idx3, const float* __restrict__ w3,
                              int Mper, float* __restrict__ dst, int ldD, int colOff)
{
    int t = blockIdx.x * blockDim.x + threadIdx.x;
    int total = BB * Mper * C;
    if (t >= total) return;
    int c = t % C; int row = t / C; int b = row / Mper;
    const int* I = idx3 + (size_t)row * 3;
    const float* Wt = w3 + (size_t)row * 3;
    const float* F = feat + (size_t)b * Nsrc * C;
    float v = Wt[0] * F[(size_t)I[0] * C + c]
            + Wt[1] * F[(size_t)I[1] * C + c]
            + Wt[2] * F[(size_t)I[2] * C + c];
    dst[(size_t)row * ldD + colOff + c] = v;
}

// ---------------- strided column copy into Acat ----------------
__global__ void copy_cols_kernel(const float* __restrict__ src, int cols, int Mtot,
                                 float* __restrict__ dst, int ldD, int colOff)
{
    int t = blockIdx.x * blockDim.x + threadIdx.x;
    int total = Mtot * cols;
    if (t >= total) return;
    int c = t % cols; int row = t / cols;
    dst[(size_t)row * ldD + colOff + c] = src[t];
}

// ---------------- host orchestration ----------------
static inline void gemm_s(cudaStream_t s, const float* A, int ldA, const float* W,
                          const float* bias, float* C, int M, int N, int Kd, int act)
{
    dim3 grid(N / 64, M / 128);
    sgemm_kernel<<<grid, 256, 0, s>>>(A, ldA, W, bias, C, M, N, Kd, act);
}

extern "C" void kernel_launch(void* const* d_in, const int* in_sizes, int n_in,
                              void* d_out, int out_size)
{
    const float* x          = (const float*)d_in[0];
    const float* pos        = (const float*)d_in[1];
    const float* w_self0    = (const float*)d_in[2];
    const float* w_edge0    = (const float*)d_in[3];
    const float* w_self1    = (const float*)d_in[4];
    const float* w_edge1    = (const float*)d_in[5];
    const float* w_self2    = (const float*)d_in[6];
    const float* w_edge2    = (const float*)d_in[7];
    const float* w_up1      = (const float*)d_in[8];
    const float* b_up1      = (const float*)d_in[9];
    const float* w_upc1_self= (const float*)d_in[10];
    const float* w_upc1_edge= (const float*)d_in[11];
    const float* w_up0      = (const float*)d_in[12];
    const float* b_up0      = (const float*)d_in[13];
    const float* w_upc0_self= (const float*)d_in[14];
    const float* w_upc0_edge= (const float*)d_in[15];
    const float* w_out      = (const float*)d_in[16];
    const float* b_out      = (const float*)d_in[17];

    float* base = nullptr;
    cudaGetSymbolAddress((void**)&base, g_buf);

    int*   idx0  = (int*)(base + OFF_IDX0);
    int*   idx1  = (int*)(base + OFF_IDX1);
    int*   idx2  = (int*)(base + OFF_IDX2);
    int*   fps1  = (int*)(base + OFF_FPS1);
    int*   fps2  = (int*)(base + OFF_FPS2);
    float* pos1  = base + OFF_POS1;
    float* pos2  = base + OFF_POS2;
    float* feat0 = base + OFF_FEAT0;
    float* fg1   = base + OFF_FG1;
    float* feat1 = base + OFF_FEAT1;
    float* fg2   = base + OFF_FG2;
    float* feat2 = base + OFF_FEAT2;
    int*   nni1  = (int*)(base + OFF_NNI1);
    float* nnw1  = base + OFF_NNW1;
    int*   nni0  = (int*)(base + OFF_NNI0);
    float* nnw0  = base + OFF_NNW0;
    float* fu1p  = base + OFF_FU1P;
    float* fu1   = base + OFF_FU1;
    float* fu0   = base + OFF_FU0;
    float* fout  = base + OFF_FOUT;
    float* Acat  = base + OFF_ACAT;
    float* Wcat  = base + OFF_WCAT;
    float* ps0   = base + OFF_PS0;
    int*   pm0   = (int*)(base + OFF_PM0);
    float* bb0   = base + OFF_BB0;
    float* ps1   = base + OFF_PS1;
    int*   pm1   = (int*)(base + OFF_PM1);
    float* bb1   = base + OFF_BB1;

    static cudaStream_t sA = [](){ cudaStream_t s; cudaStreamCreateWithFlags(&s, cudaStreamNonBlocking); return s; }();
    static cudaStream_t sB = [](){ cudaStream_t s; cudaStreamCreateWithFlags(&s, cudaStreamNonBlocking); return s; }();
    static cudaEvent_t ev0   = [](){ cudaEvent_t e; cudaEventCreateWithFlags(&e, cudaEventDisableTiming); return e; }();
    static cudaEvent_t evF1  = [](){ cudaEvent_t e; cudaEventCreateWithFlags(&e, cudaEventDisableTiming); return e; }();
    static cudaEvent_t evF2  = [](){ cudaEvent_t e; cudaEventCreateWithFlags(&e, cudaEventDisableTiming); return e; }();
    static cudaEvent_t evT0  = [](){ cudaEvent_t e; cudaEventCreateWithFlags(&e, cudaEventDisableTiming); return e; }();
    static cudaEvent_t evT1  = [](){ cudaEvent_t e; cudaEventCreateWithFlags(&e, cudaEventDisableTiming); return e; }();

    cudaStream_t s0 = 0;

    // ---- fork: Morton-binned pruned FPS chain on stream A ----
    cudaEventRecord(ev0, s0);
    cudaStreamWaitEvent(sA, ev0, 0);
    cudaStreamWaitEvent(sB, ev0, 0);
    morton_kernel<N0, 16><<<BB, 512, 0, sA>>>(pos, ps0, pm0, bb0);
    fps8_kernel<8><<<BB, 512, 0, sA>>>(pos, ps0, pm0, bb0, N0, N1, fps1, pos1);
    cudaEventRecord(evF1, sA);
    morton_kernel<N1, 8><<<BB, 512, 0, sA>>>(pos1, ps1, pm1, bb1);
    fps8_kernel<4><<<BB, 512, 0, sA>>>(pos1, ps1, pm1, bb1, N1, N2, fps2, pos2);
    cudaEventRecord(evF2, sA);

    // ---- three_nn kernels on stream B (overlap GEMM chains) ----
    cudaStreamWaitEvent(sB, evF1, 0);
    three_nn_kernel<<<dim3(N0/128, BB), 128, 0, sB>>>(pos, N0, pos1, N1, nni0, nnw0);
    cudaEventRecord(evT0, sB);
    cudaStreamWaitEvent(sB, evF2, 0);
    three_nn_kernel<<<dim3(N1/128, BB), 128, 0, sB>>>(pos1, N1, pos2, N2, nni1, nnw1);
    cudaEventRecord(evT1, sB);

    // ---- level 0 edge conv (concurrent with fps1): C=4, Kcat=12, N=64 ----
    knn_kernel<<<dim3(N0/128, BB), 128, 0, s0>>>(pos, N0, idx0);
    hbar_kernel<<<(BB*N0)/4, 128, 0, s0>>>(x, pos, idx0, N0, 4, Acat, 12);
    cudaMemcpyAsync(Wcat,         w_self0, (size_t)4*64*4, cudaMemcpyDeviceToDevice, s0);
    cudaMemcpyAsync(Wcat + 4*64,  w_edge0, (size_t)8*64*4, cudaMemcpyDeviceToDevice, s0);
    gemm_s(s0, Acat, 12, Wcat, nullptr, feat0, BB*N0, 64, 12, 1);

    // ---- join fps1; level 1 chain (concurrent with fps2) ----
    cudaStreamWaitEvent(s0, evF1, 0);
    gather_kernel<<<(BB*N1*64 + 255)/256, 256, 0, s0>>>(feat0, 64, N0, fps1, N1, fg1);
    knn_kernel<<<dim3(N1/128, BB), 128, 0, s0>>>(pos1, N1, idx1);
    hbar_kernel<<<(BB*N1)/4, 128, 0, s0>>>(fg1, pos1, idx1, N1, 64, Acat, 132);
    cudaMemcpyAsync(Wcat,          w_self1, (size_t)64*128*4, cudaMemcpyDeviceToDevice, s0);
    cudaMemcpyAsync(Wcat + 64*128, w_edge1, (size_t)68*128*4, cudaMemcpyDeviceToDevice, s0);
    gemm_s(s0, Acat, 132, Wcat, nullptr, feat1, BB*N1, 128, 132, 1);

    // ---- join fps2; level 2 edge conv: C=128, Kcat=260, N=256 ----
    cudaStreamWaitEvent(s0, evF2, 0);
    gather_kernel<<<(BB*N2*128 + 255)/256, 256, 0, s0>>>(feat1, 128, N1, fps2, N2, fg2);
    knn_kernel<<<dim3(N2/128, BB), 128, 0, s0>>>(pos2, N2, idx2);
    hbar_kernel<<<(BB*N2)/4, 128, 0, s0>>>(fg2, pos2, idx2, N2, 128, Acat, 260);
    cudaMemcpyAsync(Wcat,           w_self2, (size_t)128*256*4, cudaMemcpyDeviceToDevice, s0);
    cudaMemcpyAsync(Wcat + 128*256, w_edge2, (size_t)132*256*4, cudaMemcpyDeviceToDevice, s0);
    gemm_s(s0, Acat, 260, Wcat, nullptr, feat2, BB*N2, 256, 260, 1);

    // ---- up 1: interp feat2, cat feat1, linear ----
    cudaStreamWaitEvent(s0, evT1, 0);
    interp_kernel<<<(BB*N1*256 + 255)/256, 256, 0, s0>>>(feat2, 256, N2, nni1, nnw1, N1, Acat, 384, 0);
    copy_cols_kernel<<<(BB*N1*128 + 255)/256, 256, 0, s0>>>(feat1, 128, BB*N1, Acat, 384, 256);
    gemm_s(s0, Acat, 384, w_up1, b_up1, fu1p, BB*N1, 128, 384, 1);

    // ---- up 1 edge conv (reuse idx1): C=128, Kcat=260, N=128 ----
    hbar_kernel<<<(BB*N1)/4, 128, 0, s0>>>(fu1p, pos1, idx1, N1, 128, Acat, 260);
    cudaMemcpyAsync(Wcat,           w_upc1_self, (size_t)128*128*4, cudaMemcpyDeviceToDevice, s0);
    cudaMemcpyAsync(Wcat + 128*128, w_upc1_edge, (size_t)132*128*4, cudaMemcpyDeviceToDevice, s0);
    gemm_s(s0, Acat, 260, Wcat, nullptr, fu1, BB*N1, 128, 260, 1);

    // ---- up 0: interp fu1, cat feat0, linear ----
    cudaStreamWaitEvent(s0, evT0, 0);
    interp_kernel<<<(BB*N0*128 + 255)/256, 256, 0, s0>>>(fu1, 128, N1, nni0, nnw0, N0, Acat, 192, 0);
    copy_cols_kernel<<<(BB*N0*64 + 255)/256, 256, 0, s0>>>(feat0, 64, BB*N0, Acat, 192, 128);
    gemm_s(s0, Acat, 192, w_up0, b_up0, fu0, BB*N0, 64, 192, 1);

    // ---- up 0 edge conv (reuse idx0): C=64, Kcat=132, N=64 ----
    hbar_kernel<<<(BB*N0)/4, 128, 0, s0>>>(fu0, pos, idx0, N0, 64, Acat, 132);
    cudaMemcpyAsync(Wcat,         w_upc0_self, (size_t)64*64*4, cudaMemcpyDeviceToDevice, s0);
    cudaMemcpyAsync(Wcat + 64*64, w_upc0_edge, (size_t)68*64*4, cudaMemcpyDeviceToDevice, s0);
    gemm_s(s0, Acat, 132, Wcat, nullptr, fout, BB*N0, 64, 132, 1);

    // ---- output projection: no activation ----
    gemm_s(s0, fout, 64, w_out, b_out, (float*)d_out, BB*N0, 128, 64, 0);
}